// round 16
// baseline (speedup 1.0000x reference)
#include <cuda_runtime.h>
#include <cuda_bf16.h>
#include <cstdint>

// if_encoder: integrate-and-fire with soft reset (bit-exact vs reference scan).
//   d_in[0] input_spikes [B=64, D=4096, T=128] f32 (T contiguous)
//   d_in[1] states       [B, D] f32
//   d_in[2] threshold    scalar f32
//   d_out  = spikes [B, D, T] f32  followed by  v_final [B, D] f32
//
// FINAL converged configuration (measured: 36.0us kernel, 5.90TB/s = 74.6%
// HBM — at the measured mixed-read/write DRAM wall for this part):
//   READ : all four 4KB chunk cp.async groups issued back-to-back (one
//          uninterrupted 16KB read burst per warp); scan of chunk c starts
//          as soon as its group lands (wait_group 3-c).
//   SCAN : lane = row, XOR-swizzled smem, conflict-free LDS/STS.128,
//          reference FP order kept bit-exact (v+=x; s=v>=thr; v=fma(-s,thr,v)).
//   WRITE: deferred to segment end -> one 16KB contiguous st.global.wt burst
//          (write-through: no L2 allocation; +3% DRAM efficiency measured).
//   GRID : 32-thread blocks (1 warp, 16KB smem, 14 blocks/SM, 8192 blocks,
//          3.95 waves): finest scheduling granularity, 14 independent per-SM
//          pipelines (+2.5% vs 128-thread blocks, measured).
// No block barriers; only per-warp cp.async groups + __syncwarp.

static constexpr int B_ = 64;
static constexpr int D_ = 4096;
static constexpr int T_ = 128;
static constexpr long long ROWS = (long long)B_ * D_;   // 262144
static constexpr int BLOCK = 32;                        // 1 warp per block
static constexpr int RPW = 32;                          // rows per warp
static constexpr int F4 = T_ / 4;                       // 32 float4 per row
static constexpr int NCH = 4;                           // chunks per segment
static constexpr int CH_F4 = F4 / NCH;                  // 8 float4 per row-chunk
static constexpr int CHUNK_F4 = RPW * CH_F4;            // 256 f4 = 4KB
static constexpr int SMEM_BYTES = NCH * CHUNK_F4 * 16;  // 16384

__device__ __forceinline__ void cp_async16(uint32_t smem_addr, const void* gptr) {
    asm volatile("cp.async.cg.shared.global [%0], [%1], 16;\n"
                 :: "r"(smem_addr), "l"(gptr) : "memory");
}
__device__ __forceinline__ void cp_commit() {
    asm volatile("cp.async.commit_group;\n" ::: "memory");
}
template <int N>
__device__ __forceinline__ void cp_wait() {
    asm volatile("cp.async.wait_group %0;\n" :: "n"(N) : "memory");
}
// write-through store: do not allocate the line in L2
__device__ __forceinline__ void st_wt(float4* p, float4 f) {
    asm volatile("st.global.wt.v4.f32 [%0], {%1, %2, %3, %4};"
                 :: "l"(p), "f"(f.x), "f"(f.y), "f"(f.z), "f"(f.w) : "memory");
}

__global__ __launch_bounds__(BLOCK, 14)
void if_encoder_kernel(const float* __restrict__ x,
                       const float* __restrict__ states,
                       const float* __restrict__ thr_ptr,
                       float* __restrict__ spikes,
                       float* __restrict__ vfinal) {
    extern __shared__ __align__(16) float4 wbuf[];   // [NCH][RPW][CH_F4]

    const int lane = threadIdx.x & 31;

    const long long wrow0 = (long long)blockIdx.x * RPW;

    const float4* __restrict__ x4  = reinterpret_cast<const float4*>(x);
    float4* __restrict__       sp4 = reinterpret_cast<float4*>(spikes);

    const uint32_t sb = (uint32_t)__cvta_generic_to_shared(wbuf);

    // load-phase lane mapping: 8 lanes cover one row's 128B chunk slice
    const int lr  = lane >> 3;      // row offset within k-group
    const int lc4 = lane & 7;

    // ---- issue ALL chunk loads up front: one 16KB read burst per warp ----
    #pragma unroll
    for (int c = 0; c < NCH; ++c) {
        #pragma unroll
        for (int k = 0; k < 8; ++k) {
            const int r    = k * 4 + lr;
            const int slot = lc4 ^ (r & 7);
            const uint32_t dst = sb + (uint32_t)((c * CHUNK_F4 + r * CH_F4 + slot) << 4);
            cp_async16(dst, &x4[(wrow0 + r) * F4 + c * CH_F4 + lc4]);
        }
        cp_commit();
    }

    // scalar loads (const path) overlap the in-flight bulk reads
    const float thr = __ldg(thr_ptr);
    float v = __ldg(&states[wrow0 + lane]);
    const int sw = lane & 7;

    // ---- scan chunk c as soon as its group arrives ----
    #pragma unroll
    for (int c = 0; c < NCH; ++c) {
        if      (c == 0) cp_wait<3>();
        else if (c == 1) cp_wait<2>();
        else if (c == 2) cp_wait<1>();
        else             cp_wait<0>();
        __syncwarp();              // cross-lane cp.async data visible

        float4* const my = wbuf + c * CHUNK_F4 + lane * CH_F4;
        #pragma unroll
        for (int c4 = 0; c4 < CH_F4; ++c4) {
            float4* const p = my + (c4 ^ sw);
            const float4 xx = *p;
            float4 sp;
            v += xx.x; sp.x = (v >= thr) ? 1.0f : 0.0f; v = fmaf(-sp.x, thr, v);
            v += xx.y; sp.y = (v >= thr) ? 1.0f : 0.0f; v = fmaf(-sp.y, thr, v);
            v += xx.z; sp.z = (v >= thr) ? 1.0f : 0.0f; v = fmaf(-sp.z, thr, v);
            v += xx.w; sp.w = (v >= thr) ? 1.0f : 0.0f; v = fmaf(-sp.w, thr, v);
            *p = sp;
        }
    }
    __syncwarp();                  // all spikes visible for the store blast

    // v_final first: tiny write, overlaps the big burst below
    vfinal[wrow0 + lane] = v;

    // ---- single 16KB contiguous write-through burst per warp ----
    // full warp covers one 512B row per instruction, rows in gmem order
    #pragma unroll
    for (int r = 0; r < RPW; ++r) {
        const int c    = lane >> 3;          // chunk holding this lane's f4
        const int slot = (lane & 7) ^ (r & 7);
        const float4 f = wbuf[c * CHUNK_F4 + r * CH_F4 + slot];
        st_wt(&sp4[(wrow0 + r) * F4 + lane], f);
    }
}

extern "C" void kernel_launch(void* const* d_in, const int* in_sizes, int n_in,
                              void* d_out, int out_size) {
    const float* x      = (const float*)d_in[0];
    const float* states = (const float*)d_in[1];
    const float* thr    = (const float*)d_in[2];

    float* out    = (float*)d_out;
    float* spikes = out;
    float* vfin   = out + ROWS * T_;   // out layout: spikes then v_final

    static bool attr_set = false;   // idempotent device-state setup (not work)
    if (!attr_set) {
        cudaFuncSetAttribute(if_encoder_kernel,
                             cudaFuncAttributeMaxDynamicSharedMemorySize,
                             SMEM_BYTES);
        attr_set = true;
    }

    const int grid = (int)(ROWS / RPW);   // 8192 single-warp blocks
    if_encoder_kernel<<<grid, BLOCK, SMEM_BYTES>>>(x, states, thr, spikes, vfin);
}